// round 9
// baseline (speedup 1.0000x reference)
#include <cuda_runtime.h>
#include <cstdint>

// WanRotaryPosEmbedS2VStyle: build (freqs_cos, freqs_sin) grids.
//
//   output: cos (1, n_tok, 1, 128) then sin; n_tok = F*3600.
//   Per token (f,y,x): ch [0,44)=t_tab[pt], [44,86)=h_tab[y], [86,128)=w_tab[x].
//
// R9: every per-thread-STG variant (R3/R5/R7/R8) plateaus at ~14.5us with
// L1tex pinned ~55% — the STG wavefront path is the wall. Route the 81MB
// write stream through SMEM + cp.async.bulk (async/TMA proxy) instead:
// 16-token items (8KB cos + 8KB sin), double-buffered (32KB/block, 7
// blocks/SM), wait_group 1 pipelining so fills overlap in-flight bulk
// stores. L2-rate floor ~7us.

#define T_DIM 44
#define H_DIM 42
#define W_DIM 42
#define GRID_W 60
#define GRID_HW 3600
#define FIXED_REF 30

#define TOK_ITEM 16                         // tokens per item (16 | 3600)
#define ITEM_FLOATS (TOK_ITEM * 128)        // 2048 floats = 8192 B
#define STAGE_FLOATS (2 * ITEM_FLOATS)      // cos + sin = 4096 floats
#define SMEM_BYTES (2 * STAGE_FLOATS * 4)   // 2 stages = 32768 B

__global__ __launch_bounds__(256)
void wan_rope_kernel(
    const float* __restrict__ tcos, const float* __restrict__ hcos,
    const float* __restrict__ wcos, const float* __restrict__ tsin,
    const float* __restrict__ hsin, const float* __restrict__ wsin,
    const int*   __restrict__ nvf_p,
    float* __restrict__ out, int n_tok, int n_items)
{
    extern __shared__ float smem[];         // 2 stages of [cos|sin]

    const int wid  = threadIdx.x >> 5;
    const int lane = threadIdx.x & 31;
    const int d0   = lane << 2;             // channels [d0, d0+4)

    const int video_pp = __ldg(nvf_p);

    // per-lane fixed predicates: which table each even pair lives in
    const int dA = d0, dB = d0 + 2;
    const bool iswA = (dA >= T_DIM + H_DIM);
    const bool iswB = (dB >= T_DIM + H_DIM);
    const bool ishA = (dA >= T_DIM) && !iswA;
    const bool ishB = (dB >= T_DIM) && !iswB;

    int it = 0;
    for (int item = blockIdx.x; item < n_items; item += gridDim.x, ++it) {
        const int stage = it & 1;
        float* smc = smem + stage * STAGE_FLOATS;
        float* sms = smc + ITEM_FLOATS;

        // Reuse guard: allow at most 1 bulk group in flight (the other stage's).
        if (threadIdx.x == 0)
            asm volatile("cp.async.bulk.wait_group 1;" ::: "memory");
        __syncthreads();

        // ---- decode item ----
        const int tok0 = item * TOK_ITEM;
        const int f    = tok0 / GRID_HW;
        const int rem  = tok0 - f * GRID_HW;
        const int y    = rem / GRID_W;
        const int x0   = rem - y * GRID_W;  // multiple of TOK_ITEM? no — of 16 within 60? 60%16!=0
        const int pt   = (f < video_pp) ? f : FIXED_REF;

        const int tbase = pt * T_DIM;
        const int hbase = y * H_DIM - T_DIM;

        // invariant halves for this item (t/h) — note: an item may straddle a
        // row boundary only in x, never in (f,y)? 3600 % 16 == 0 but 60 % 16 != 0,
        // so x wraps within the same frame only when y increments — handle by
        // recomputing per token below for full generality on w AND h.
        const float2* pcwA = reinterpret_cast<const float2*>(wcos + dA - (T_DIM + H_DIM));
        const float2* pswA = reinterpret_cast<const float2*>(wsin + dA - (T_DIM + H_DIM));
        const float2* pcwB = reinterpret_cast<const float2*>(wcos + dB - (T_DIM + H_DIM));
        const float2* pswB = reinterpret_cast<const float2*>(wsin + dB - (T_DIM + H_DIM));

        // t-half never changes within an item (f fixed: 3600 % 16 == 0).
        float2 ctA = make_float2(0.f, 0.f), stA = ctA, ctB = ctA, stB = ctA;
        if (!iswA) {
            const int off = ishA ? 0 : (tbase + dA);
            if (!ishA) {
                ctA = __ldg(reinterpret_cast<const float2*>(tcos + off));
                stA = __ldg(reinterpret_cast<const float2*>(tsin + off));
            }
        }
        if (!iswB) {
            const int off = ishB ? 0 : (tbase + dB);
            if (!ishB) {
                ctB = __ldg(reinterpret_cast<const float2*>(tcos + off));
                stB = __ldg(reinterpret_cast<const float2*>(tsin + off));
            }
        }

        // ---- fill stage: warp wid handles tokens xi = wid, wid+8 ----
        for (int xi = wid; xi < TOK_ITEM; xi += 8) {
            // x may wrap rows within the item (60 % 16 != 0)
            int xx = x0 + xi;
            int yy = y;
            if (xx >= GRID_W) { xx -= GRID_W; yy += 1; }
            const int hb = yy * H_DIM - T_DIM;
            const int wmul = xx * W_DIM >> 1;   // float2 index base for w row

            float2 cA, sA, cB, sB;
            if (iswA)      { cA = __ldg(pcwA + wmul); sA = __ldg(pswA + wmul); }
            else if (ishA) { cA = __ldg(reinterpret_cast<const float2*>(hcos + hb + dA));
                             sA = __ldg(reinterpret_cast<const float2*>(hsin + hb + dA)); }
            else           { cA = ctA; sA = stA; }
            if (iswB)      { cB = __ldg(pcwB + wmul); sB = __ldg(pswB + wmul); }
            else if (ishB) { cB = __ldg(reinterpret_cast<const float2*>(hcos + hb + dB));
                             sB = __ldg(reinterpret_cast<const float2*>(hsin + hb + dB)); }
            else           { cB = ctB; sB = stB; }

            const int off = xi * 128 + d0;
            *reinterpret_cast<float4*>(smc + off) = make_float4(cA.x, cA.y, cB.x, cB.y);
            *reinterpret_cast<float4*>(sms + off) = make_float4(sA.x, sA.y, sB.x, sB.y);
        }

        __syncthreads();

        if (threadIdx.x == 0) {
            asm volatile("fence.proxy.async.shared::cta;" ::: "memory");
            uint32_t sc_addr, ss_addr;
            asm("{ .reg .u64 t; cvta.to.shared.u64 t, %1; cvt.u32.u64 %0, t; }"
                : "=r"(sc_addr) : "l"(smc));
            asm("{ .reg .u64 t; cvta.to.shared.u64 t, %1; cvt.u32.u64 %0, t; }"
                : "=r"(ss_addr) : "l"(sms));
            float* gc = out + (size_t)tok0 * 128;
            float* gs = gc + (size_t)n_tok * 128;
            asm volatile("cp.async.bulk.global.shared::cta.bulk_group [%0], [%1], %2;"
                         :: "l"(gc), "r"(sc_addr), "n"(ITEM_FLOATS * 4) : "memory");
            asm volatile("cp.async.bulk.global.shared::cta.bulk_group [%0], [%1], %2;"
                         :: "l"(gs), "r"(ss_addr), "n"(ITEM_FLOATS * 4) : "memory");
            asm volatile("cp.async.bulk.commit_group;" ::: "memory");
        }
    }

    // SMEM must outlive in-flight bulk reads.
    if (threadIdx.x == 0)
        asm volatile("cp.async.bulk.wait_group 0;" ::: "memory");
    __syncthreads();
}

extern "C" void kernel_launch(void* const* d_in, const int* in_sizes, int n_in,
                              void* d_out, int out_size)
{
    // 0: hidden_states (unused)
    // 1: freq_t_cos  2: freq_h_cos  3: freq_w_cos
    // 4: freq_t_sin  5: freq_h_sin  6: freq_w_sin
    // 7: num_video_frames (int32)   8: num_ref_frames (int32)
    const float* tcos = (const float*)d_in[1];
    const float* hcos = (const float*)d_in[2];
    const float* wcos = (const float*)d_in[3];
    const float* tsin = (const float*)d_in[4];
    const float* hsin = (const float*)d_in[5];
    const float* wsin = (const float*)d_in[6];
    const int*   nvf  = (const int*)d_in[7];

    float* out = (float*)d_out;

    const int n_tok   = out_size / 256;     // out_size = 2 * n_tok * 128
    const int n_items = n_tok / TOK_ITEM;   // 3600 % 16 == 0

    static int smem_cfgd = 0;
    if (!smem_cfgd) {
        cudaFuncSetAttribute(wan_rope_kernel,
                             cudaFuncAttributeMaxDynamicSharedMemorySize,
                             SMEM_BYTES);
        smem_cfgd = 1;
    }

    const int blocks = 148 * 7;             // 7 x 32KB = 224KB/SM
    wan_rope_kernel<<<blocks, 256, SMEM_BYTES>>>(tcos, hcos, wcos, tsin, hsin,
                                                 wsin, nvf, out, n_tok, n_items);
}

// round 10
// speedup vs baseline: 1.2652x; 1.2652x over previous
#include <cuda_runtime.h>
#include <cstdint>

// WanRotaryPosEmbedS2VStyle: build (freqs_cos, freqs_sin) grids.
//
//   output: cos (1, n_tok, 1, 128) then sin; n_tok = F*3600.
//   Per token (f,y,x): ch [0,44)=t_tab[pt], [44,86)=h_tab[y], [86,128)=w_tab[x].
//   Tables are repeat(.,2): each aligned even pair is (v,v) -> one scalar.
//
// R10: R9 (bulk-store) regressed again — abandoned. Plateau analysis: the
// per-thread-STG kernels were bounded by per-warp serial latency across 2.5
// waves of short warps. Fix: zero-load rotation body (R8) x X_PER=20
// (3 warps per 60-token row, single wave of 3960 warps, 495 blocks).
// Per token: 8 FFMA + 2 STG.128; prologue (~9 LDG + divides) amortized 20x.
// w-lanes advance by rotation: cos((x+1)t) = c*cosT - s*sinT etc., step from
// w-table row 1; t/h lanes use identity step (1,0).

#define T_DIM 44
#define H_DIM 42
#define W_DIM 42
#define GRID_W 60
#define GRID_HW 3600
#define FIXED_REF 30
#define X_PER 20           // tokens per warp (20 | 60 -> never crosses a row)

__global__ __launch_bounds__(256)
void wan_rope_kernel(
    const float* __restrict__ tcos, const float* __restrict__ hcos,
    const float* __restrict__ wcos, const float* __restrict__ tsin,
    const float* __restrict__ hsin, const float* __restrict__ wsin,
    const int*   __restrict__ nvf_p,
    float* __restrict__ out, int n_tok, int n_warps)
{
    const int gtid = blockIdx.x * blockDim.x + threadIdx.x;
    const int w    = gtid >> 5;
    if (w >= n_warps) return;
    const int lane = gtid & 31;
    const int d0   = lane << 2;            // channels [d0, d0+4)

    const int tok0 = w * X_PER;            // 20 tokens, same (f,y)
    const int f    = tok0 / GRID_HW;
    const int rem  = tok0 - f * GRID_HW;
    const int y    = rem / GRID_W;
    const int x0   = rem - y * GRID_W;

    const int video_pp = __ldg(nvf_p);
    const int pt = (f < video_pp) ? f : FIXED_REF;

    const int tbase = pt * T_DIM;
    const int hbase = y * H_DIM - T_DIM;
    const int wbase = x0 * W_DIM - (T_DIM + H_DIM);

    const int dA = d0;                     // first even pair
    const int dB = d0 + 2;                 // second even pair
    const bool iswA = (dA >= T_DIM + H_DIM);
    const bool iswB = (dB >= T_DIM + H_DIM);

    // initial scalar values (pairs duplicated (v,v): load one float)
    const float* pcA = iswA ? (wcos + wbase + dA)
                     : (dA >= T_DIM) ? (hcos + hbase + dA) : (tcos + tbase + dA);
    const float* psA = iswA ? (wsin + wbase + dA)
                     : (dA >= T_DIM) ? (hsin + hbase + dA) : (tsin + tbase + dA);
    const float* pcB = iswB ? (wcos + wbase + dB)
                     : (dB >= T_DIM) ? (hcos + hbase + dB) : (tcos + tbase + dB);
    const float* psB = iswB ? (wsin + wbase + dB)
                     : (dB >= T_DIM) ? (hsin + hbase + dB) : (tsin + tbase + dB);

    float cA = __ldg(pcA), sA = __ldg(psA);
    float cB = __ldg(pcB), sB = __ldg(psB);

    // rotation step per pair: w-table row 1, same column; identity for t/h
    const float stcA = iswA ? __ldg(wcos + W_DIM + dA - (T_DIM + H_DIM)) : 1.0f;
    const float stsA = iswA ? __ldg(wsin + W_DIM + dA - (T_DIM + H_DIM)) : 0.0f;
    const float stcB = iswB ? __ldg(wcos + W_DIM + dB - (T_DIM + H_DIM)) : 1.0f;
    const float stsB = iswB ? __ldg(wsin + W_DIM + dB - (T_DIM + H_DIM)) : 0.0f;
    const float nstsA = -stsA, nstsB = -stsB;

    float4* oc4 = reinterpret_cast<float4*>(out + (size_t)tok0 * 128 + d0);
    float4* os4 = reinterpret_cast<float4*>(out + (size_t)(n_tok + tok0) * 128 + d0);

#pragma unroll
    for (int xi = 0; xi < X_PER; xi++) {
        oc4[xi * 32] = make_float4(cA, cA, cB, cB);
        os4[xi * 32] = make_float4(sA, sA, sB, sB);
        if (xi + 1 < X_PER) {              // rotate for next token (no loads)
            const float mA  = sA * nstsA, m2A = cA * stsA;
            cA = fmaf(cA, stcA, mA);
            sA = fmaf(sA, stcA, m2A);
            const float mB  = sB * nstsB, m2B = cB * stsB;
            cB = fmaf(cB, stcB, mB);
            sB = fmaf(sB, stcB, m2B);
        }
    }
}

extern "C" void kernel_launch(void* const* d_in, const int* in_sizes, int n_in,
                              void* d_out, int out_size)
{
    // 0: hidden_states (unused)
    // 1: freq_t_cos  2: freq_h_cos  3: freq_w_cos
    // 4: freq_t_sin  5: freq_h_sin  6: freq_w_sin
    // 7: num_video_frames (int32)   8: num_ref_frames (int32)
    const float* tcos = (const float*)d_in[1];
    const float* hcos = (const float*)d_in[2];
    const float* wcos = (const float*)d_in[3];
    const float* tsin = (const float*)d_in[4];
    const float* hsin = (const float*)d_in[5];
    const float* wsin = (const float*)d_in[6];
    const int*   nvf  = (const int*)d_in[7];

    float* out = (float*)d_out;

    const int n_tok   = out_size / 256;    // out_size = 2 * n_tok * 128
    const int n_warps = n_tok / X_PER;     // 3600 % 20 == 0
    const int threads = 256;
    const int blocks  = (n_warps * 32 + threads - 1) / threads;  // 495

    wan_rope_kernel<<<blocks, threads>>>(tcos, hcos, wcos, tsin, hsin, wsin,
                                         nvf, out, n_tok, n_warps);
}

// round 11
// speedup vs baseline: 1.4186x; 1.1212x over previous
#include <cuda_runtime.h>
#include <cstdint>

// WanRotaryPosEmbedS2VStyle: build (freqs_cos, freqs_sin) grids.
//
//   output: cos (1, n_tok, 1, 128) then sin; n_tok = F*3600.
//   Per token (f,y,x): ch [0,44)=t_tab[pt], [44,86)=h_tab[y], [86,128)=w_tab[x].
//   Tables are repeat(.,2): each aligned even pair is (v,v) -> one scalar.
//
// R11: R10 (X_PER=20) starved the chip (3960 warps, occ 32%). Same zero-load
// rotation body, X_PER=10 -> 7920 warps = 990 blocks = one full wave at ~83%
// warp capacity. Per token: 8 FFMA + 2 STG.128; prologue amortized 10x.
// If this still lands ~14us @ L2~50%, the L2 write path is the confirmed
// roofline (cache-policy attack next), since instruction count, loads, and
// occupancy have all been independently eliminated as factors.

#define T_DIM 44
#define H_DIM 42
#define W_DIM 42
#define GRID_W 60
#define GRID_HW 3600
#define FIXED_REF 30
#define X_PER 10           // tokens per warp (10 | 60 -> never crosses a row)

__global__ __launch_bounds__(256)
void wan_rope_kernel(
    const float* __restrict__ tcos, const float* __restrict__ hcos,
    const float* __restrict__ wcos, const float* __restrict__ tsin,
    const float* __restrict__ hsin, const float* __restrict__ wsin,
    const int*   __restrict__ nvf_p,
    float* __restrict__ out, int n_tok, int n_warps)
{
    const int gtid = blockIdx.x * blockDim.x + threadIdx.x;
    const int w    = gtid >> 5;
    if (w >= n_warps) return;
    const int lane = gtid & 31;
    const int d0   = lane << 2;            // channels [d0, d0+4)

    const int tok0 = w * X_PER;            // 10 tokens, same (f,y)
    const int f    = tok0 / GRID_HW;
    const int rem  = tok0 - f * GRID_HW;
    const int y    = rem / GRID_W;
    const int x0   = rem - y * GRID_W;

    const int video_pp = __ldg(nvf_p);
    const int pt = (f < video_pp) ? f : FIXED_REF;

    const int tbase = pt * T_DIM;
    const int hbase = y * H_DIM - T_DIM;
    const int wbase = x0 * W_DIM - (T_DIM + H_DIM);

    const int dA = d0;                     // first even pair
    const int dB = d0 + 2;                 // second even pair
    const bool iswA = (dA >= T_DIM + H_DIM);
    const bool iswB = (dB >= T_DIM + H_DIM);

    // initial scalar values (pairs duplicated (v,v): load one float)
    const float* pcA = iswA ? (wcos + wbase + dA)
                     : (dA >= T_DIM) ? (hcos + hbase + dA) : (tcos + tbase + dA);
    const float* psA = iswA ? (wsin + wbase + dA)
                     : (dA >= T_DIM) ? (hsin + hbase + dA) : (tsin + tbase + dA);
    const float* pcB = iswB ? (wcos + wbase + dB)
                     : (dB >= T_DIM) ? (hcos + hbase + dB) : (tcos + tbase + dB);
    const float* psB = iswB ? (wsin + wbase + dB)
                     : (dB >= T_DIM) ? (hsin + hbase + dB) : (tsin + tbase + dB);

    float cA = __ldg(pcA), sA = __ldg(psA);
    float cB = __ldg(pcB), sB = __ldg(psB);

    // rotation step per pair: w-table row 1, same column; identity for t/h
    const float stcA = iswA ? __ldg(wcos + W_DIM + dA - (T_DIM + H_DIM)) : 1.0f;
    const float stsA = iswA ? __ldg(wsin + W_DIM + dA - (T_DIM + H_DIM)) : 0.0f;
    const float stcB = iswB ? __ldg(wcos + W_DIM + dB - (T_DIM + H_DIM)) : 1.0f;
    const float stsB = iswB ? __ldg(wsin + W_DIM + dB - (T_DIM + H_DIM)) : 0.0f;
    const float nstsA = -stsA, nstsB = -stsB;

    float4* oc4 = reinterpret_cast<float4*>(out + (size_t)tok0 * 128 + d0);
    float4* os4 = reinterpret_cast<float4*>(out + (size_t)(n_tok + tok0) * 128 + d0);

#pragma unroll
    for (int xi = 0; xi < X_PER; xi++) {
        oc4[xi * 32] = make_float4(cA, cA, cB, cB);
        os4[xi * 32] = make_float4(sA, sA, sB, sB);
        if (xi + 1 < X_PER) {              // rotate for next token (no loads)
            const float mA  = sA * nstsA, m2A = cA * stsA;
            cA = fmaf(cA, stcA, mA);
            sA = fmaf(sA, stcA, m2A);
            const float mB  = sB * nstsB, m2B = cB * stsB;
            cB = fmaf(cB, stcB, mB);
            sB = fmaf(sB, stcB, m2B);
        }
    }
}

extern "C" void kernel_launch(void* const* d_in, const int* in_sizes, int n_in,
                              void* d_out, int out_size)
{
    // 0: hidden_states (unused)
    // 1: freq_t_cos  2: freq_h_cos  3: freq_w_cos
    // 4: freq_t_sin  5: freq_h_sin  6: freq_w_sin
    // 7: num_video_frames (int32)   8: num_ref_frames (int32)
    const float* tcos = (const float*)d_in[1];
    const float* hcos = (const float*)d_in[2];
    const float* wcos = (const float*)d_in[3];
    const float* tsin = (const float*)d_in[4];
    const float* hsin = (const float*)d_in[5];
    const float* wsin = (const float*)d_in[6];
    const int*   nvf  = (const int*)d_in[7];

    float* out = (float*)d_out;

    const int n_tok   = out_size / 256;    // out_size = 2 * n_tok * 128
    const int n_warps = n_tok / X_PER;     // 3600 % 10 == 0
    const int threads = 256;
    const int blocks  = (n_warps * 32 + threads - 1) / threads;  // 990

    wan_rope_kernel<<<blocks, threads>>>(tcos, hcos, wcos, tsin, hsin, wsin,
                                         nvf, out, n_tok, n_warps);
}